// round 15
// baseline (speedup 1.0000x reference)
#include <cuda_runtime.h>
#include <cuda_fp16.h>
#include <cstddef>
#include <cstdint>

#define VOCAB 100000
#define EMBED 128
#define STORY 50
#define SENT  64
#define BATCH 64
#define QLEN  16
#define HOPS  3

#define VT     128
#define NBLK_V ((VOCAB + VT - 1) / VT)   // 782
#define PAD    132
#define PADK   68
#define GRID_L 304
#define BSBLK  (BATCH * STORY / 4)       // 800 blocks per h-slice

// ---------------- scratch (device globals: allocation-free) ----------------
__device__ float  g_u[BATCH * EMBED];
__device__ __half g_mw[HOPS][BATCH * STORY * EMBED];   // fp16 scratch
__device__ __half g_cs[HOPS][BATCH * STORY * EMBED];
__device__ float2 g_pp[BATCH * GRID_L];                // (max, sumexp) per (b, block)

// ---------------- mma + cp.async helpers ----------------
__device__ __forceinline__ void mma_tf32(float d[4], const uint32_t a[4],
                                         uint32_t b0, uint32_t b1) {
    asm volatile(
        "mma.sync.aligned.m16n8k8.row.col.f32.tf32.tf32.f32 "
        "{%0,%1,%2,%3}, {%4,%5,%6,%7}, {%8,%9}, {%0,%1,%2,%3};"
        : "+f"(d[0]), "+f"(d[1]), "+f"(d[2]), "+f"(d[3])
        : "r"(a[0]), "r"(a[1]), "r"(a[2]), "r"(a[3]), "r"(b0), "r"(b1));
}
__device__ __forceinline__ void cp16(uint32_t dst, const void* src) {
    asm volatile("cp.async.cg.shared.global [%0], [%1], 16;" :: "r"(dst), "l"(src));
}
#define CP_COMMIT() asm volatile("cp.async.commit_group;" ::: "memory")
#define CP_WAIT1()  asm volatile("cp.async.wait_group 1;" ::: "memory")

__device__ __forceinline__ uint32_t pack_h2(float a, float b) {
    __half2 h = __float22half2_rn(make_float2(a, b));
    return *reinterpret_cast<uint32_t*>(&h);
}

// ---------------- K2: fused gather-reduce, h-major 1D grid ----------------
__global__ void __launch_bounds__(128, 8) k_gather(const int* __restrict__ x,
                                                   const float* __restrict__ A,
                                                   const float* __restrict__ TA,
                                                   const float* __restrict__ TC) {
    const int t    = threadIdx.x;
    const int w    = t >> 5, lane = t & 31;
    const int blk  = blockIdx.x;
    const int h    = blk / BSBLK;
    const int bsb  = blk - h * BSBLK;
    const int bs   = bsb * 4 + w;
    const int s    = bs % STORY;

    __shared__ int idx[4][SENT];
    ((int*)idx)[t]       = x[bsb * 4 * SENT + t];
    ((int*)idx)[t + 128] = x[bsb * 4 * SENT + t + 128];
    __syncthreads();

    const float* __restrict__ Ah = A + (size_t)h * VOCAB * EMBED;
    const int c4 = lane * 4;

    float4 pp = make_float4(0.f, 0.f, 0.f, 0.f);   // P
    float4 ff = make_float4(0.f, 0.f, 0.f, 0.f);   // F

#pragma unroll 8
    for (int j = 0; j < SENT; ++j) {
        const float4 a = *(const float4*)(Ah + (size_t)idx[w][j] * EMBED + c4);
        const float fj = (float)(j + 1) * (1.0f / SENT);
        pp.x += a.x; pp.y += a.y; pp.z += a.z; pp.w += a.w;
        ff.x = fmaf(a.x, fj, ff.x);
        ff.y = fmaf(a.y, fj, ff.y);
        ff.z = fmaf(a.z, fj, ff.z);
        ff.w = fmaf(a.w, fj, ff.w);
    }

    if (h < HOPS) {
        const float kf0 = (float)(c4 + 1) * (1.0f / EMBED);
        const float kf1 = (float)(c4 + 2) * (1.0f / EMBED);
        const float kf2 = (float)(c4 + 3) * (1.0f / EMBED);
        const float kf3 = (float)(c4 + 4) * (1.0f / EMBED);
        const float4 ta4 = *(const float4*)(TA + s * EMBED + c4);
        float4 wp;
        wp.x = (pp.x - ff.x) - kf0 * fmaf(-2.f, ff.x, pp.x) + ta4.x;
        wp.y = (pp.y - ff.y) - kf1 * fmaf(-2.f, ff.y, pp.y) + ta4.y;
        wp.z = (pp.z - ff.z) - kf2 * fmaf(-2.f, ff.z, pp.z) + ta4.z;
        wp.w = (pp.w - ff.w) - kf3 * fmaf(-2.f, ff.w, pp.w) + ta4.w;
        const uint2 pk = make_uint2(pack_h2(wp.x, wp.y), pack_h2(wp.z, wp.w));
        __stcs(reinterpret_cast<uint2*>(g_mw[h] + (size_t)bs * EMBED + c4), pk);
    }
    if (h > 0) {
        const float4 tc4 = *(const float4*)(TC + s * EMBED + c4);
        pp.x += tc4.x; pp.y += tc4.y; pp.z += tc4.z; pp.w += tc4.w;
        const uint2 pk = make_uint2(pack_h2(pp.x, pp.y), pack_h2(pp.z, pp.w));
        __stcs(reinterpret_cast<uint2*>(g_cs[h - 1] + (size_t)bs * EMBED + c4), pk);
    }
}

// ---------------- K3: u0 + 3 hops; fp16 scratch reads, last-use (.cs) ------
__global__ void __launch_bounds__(128) k_hops(const int* __restrict__ q,
                                              const float* __restrict__ A) {
    const int b = blockIdx.x;
    const int t = threadIdx.x;     // 128
    const int w = t >> 5, lane = t & 31;

    __shared__ float u[EMBED];
    __shared__ float sc[STORY];

    {
        float acc = 0.f;
#pragma unroll
        for (int j = 0; j < QLEN; ++j) {
            const int idx = __ldg(q + b * QLEN + j);
            acc += __ldg(A + (size_t)idx * EMBED + t);
        }
        u[t] = acc;
    }
    __syncthreads();

    for (int h = 0; h < HOPS; ++h) {
        const __half* __restrict__ m = g_mw[h] + (size_t)b * STORY * EMBED;
        const __half* __restrict__ c = g_cs[h] + (size_t)b * STORY * EMBED;

        for (int s = w; s < STORY; s += 4) {
            const __half* mr = m + s * EMBED;
            float d = __half2float(__ldcs(mr + lane))      * u[lane]
                    + __half2float(__ldcs(mr + lane + 32)) * u[lane + 32]
                    + __half2float(__ldcs(mr + lane + 64)) * u[lane + 64]
                    + __half2float(__ldcs(mr + lane + 96)) * u[lane + 96];
#pragma unroll
            for (int o = 16; o; o >>= 1) d += __shfl_xor_sync(0xffffffffu, d, o);
            if (lane == 0) sc[s] = d;
        }
        __syncthreads();

        if (t < 32) {
            float v0 = sc[t];
            float v1 = (t + 32 < STORY) ? sc[t + 32] : -3.4e38f;
            float mx = fmaxf(v0, v1);
#pragma unroll
            for (int o = 16; o; o >>= 1) mx = fmaxf(mx, __shfl_xor_sync(0xffffffffu, mx, o));
            float e0 = __expf(v0 - mx);
            float e1 = (t + 32 < STORY) ? __expf(v1 - mx) : 0.f;
            float sum = e0 + e1;
#pragma unroll
            for (int o = 16; o; o >>= 1) sum += __shfl_xor_sync(0xffffffffu, sum, o);
            float inv = 1.0f / sum;
            sc[t] = e0 * inv;
            if (t + 32 < STORY) sc[t + 32] = e1 * inv;
        }
        __syncthreads();

        float acc = u[t];
        for (int s = 0; s < STORY; ++s)
            acc = fmaf(sc[s], __half2float(__ldcs(c + s * EMBED + t)), acc);
        u[t] = acc;
        __syncthreads();
    }
    g_u[b * EMBED + t] = u[t];
}

// ---------------- K4a: persistent tf32-HMMA logits, running (m,s) partials --
#define SU_F   (BATCH * PAD)           // 8448
#define SAC_F  (VT * PADK)             // 8704
#define RED_O  (SU_F + 2 * SAC_F)      // 25856
#define SMEM_LOGITS ((RED_O + 512) * 4)   // 105472

__global__ void __launch_bounds__(256, 2) k_logits(const float* __restrict__ A3,
                                                   float* __restrict__ out) {
    extern __shared__ float sh[];
    float* sU   = sh;
    float* redm = sh + RED_O;           // [4][64]
    float* reds = redm + 256;           // [4][64]

    const int t = threadIdx.x, wid = t >> 5, lane = t & 31;
    const int g = lane >> 2, t4 = lane & 3;
    const int wv = wid & 3, wb = wid >> 2;
    const int blk = blockIdx.x;

    const uint32_t smem_b = (uint32_t)__cvta_generic_to_shared(sh);
    const uint32_t sU_b   = smem_b;
    const uint32_t sA_b   = smem_b + SU_F * 4;

    int ntiles = 0;
    for (int tile = blk; tile < NBLK_V; tile += GRID_L) ++ntiles;
    if (ntiles == 0) return;
    const int S = ntiles * 2;

    auto prefA = [&](int buf, int s) {
        const int tile = blk + (s >> 1) * GRID_L;
        const int v0 = tile * VT, c = (s & 1) * 64;
        const uint32_t dst0 = sA_b + buf * (SAC_F * 4);
#pragma unroll
        for (int it = 0; it < 8; ++it) {
            const int i = t + it * 256;
            const int row = i >> 4, col = i & 15;
            int gr = v0 + row; if (gr > VOCAB - 1) gr = VOCAB - 1;
            cp16(dst0 + (row * PADK + col * 4) * 4,
                 A3 + (size_t)gr * EMBED + c + col * 4);
        }
    };

#pragma unroll
    for (int it = 0; it < 8; ++it) {
        const int i = t + it * 256;
        const int row = i >> 5, col = i & 31;
        cp16(sU_b + (row * PAD + col * 4) * 4, g_u + row * EMBED + col * 4);
    }
    prefA(0, 0);
    CP_COMMIT();
    if (S > 1) { prefA(1, 1); }
    CP_COMMIT();

    float acc[2][4][4];
#pragma unroll
    for (int m = 0; m < 2; ++m)
#pragma unroll
        for (int n = 0; n < 4; ++n)
#pragma unroll
            for (int e = 0; e < 4; ++e) acc[m][n][e] = 0.f;

    float run_m = -3.4e38f, run_s = 0.f;   // per-b running (t < BATCH only)

    const uint32_t* Ub = (const uint32_t*)sU + (wb * 32 + g) * PAD + t4;

    for (int s = 0; s < S; ++s) {
        CP_WAIT1();
        __syncthreads();

        const int buf = s & 1, ksel = s & 1;
        const uint32_t* Bb = (const uint32_t*)(sh + SU_F + buf * SAC_F)
                           + (wv * 32 + g) * PADK + t4;
        const int kofs = ksel * 64;

#pragma unroll
        for (int ks = 0; ks < 8; ++ks) {
            const int k0 = ks * 8;
            uint32_t a[2][4];
#pragma unroll
            for (int m = 0; m < 2; ++m) {
                const uint32_t* p = Ub + m * 16 * PAD + kofs + k0;
                a[m][0] = p[0];
                a[m][1] = p[8 * PAD];
                a[m][2] = p[4];
                a[m][3] = p[8 * PAD + 4];
            }
#pragma unroll
            for (int n = 0; n < 4; ++n) {
                const uint32_t* p = Bb + n * 8 * PADK + k0;
                const uint32_t b0 = p[0], b1 = p[4];
                mma_tf32(acc[0][n], a[0], b0, b1);
                mma_tf32(acc[1][n], a[1], b0, b1);
            }
        }
        __syncthreads();

        if (s + 2 < S) prefA(buf, s + 2);
        CP_COMMIT();

        if (s & 1) {
            const int tile = blk + (s >> 1) * GRID_L;
            const int v0 = tile * VT;

#pragma unroll
            for (int m = 0; m < 2; ++m) {
                const int b0r = wb * 32 + m * 16 + g;
#pragma unroll
                for (int n = 0; n < 4; ++n) {
                    const int vv = v0 + wv * 32 + n * 8 + t4 * 2;
                    if (vv < VOCAB) {
                        *(float2*)(out + (size_t)b0r * VOCAB + vv) =
                            make_float2(acc[m][n][0], acc[m][n][1]);
                        *(float2*)(out + (size_t)(b0r + 8) * VOCAB + vv) =
                            make_float2(acc[m][n][2], acc[m][n][3]);
                    }
                }
            }

#pragma unroll
            for (int m = 0; m < 2; ++m)
#pragma unroll
                for (int half = 0; half < 2; ++half) {
                    float mx = -3.4e38f;
#pragma unroll
                    for (int n = 0; n < 4; ++n) {
                        const int vv = v0 + wv * 32 + n * 8 + t4 * 2;
                        if (vv < VOCAB)
                            mx = fmaxf(mx, fmaxf(acc[m][n][half * 2],
                                                 acc[m][n][half * 2 + 1]));
                    }
                    mx = fmaxf(mx, __shfl_xor_sync(0xffffffffu, mx, 1));
                    mx = fmaxf(mx, __shfl_xor_sync(0xffffffffu, mx, 2));
                    if (t4 == 0) redm[wv * 64 + wb * 32 + m * 16 + half * 8 + g] = mx;
                }
            __syncthreads();

#pragma unroll
            for (int m = 0; m < 2; ++m)
#pragma unroll
                for (int half = 0; half < 2; ++half) {
                    const int bb = wb * 32 + m * 16 + half * 8 + g;
                    const float bm = fmaxf(fmaxf(redm[bb], redm[64 + bb]),
                                           fmaxf(redm[128 + bb], redm[192 + bb]));
                    float e = 0.f;
#pragma unroll
                    for (int n = 0; n < 4; ++n) {
                        const int vv = v0 + wv * 32 + n * 8 + t4 * 2;
                        if (vv < VOCAB)
                            e += __expf(acc[m][n][half * 2] - bm) +
                                 __expf(acc[m][n][half * 2 + 1] - bm);
                    }
                    e += __shfl_xor_sync(0xffffffffu, e, 1);
                    e += __shfl_xor_sync(0xffffffffu, e, 2);
                    if (t4 == 0) reds[wv * 64 + bb] = e;
                }
            __syncthreads();

            if (t < BATCH) {
                const float bm = fmaxf(fmaxf(redm[t], redm[64 + t]),
                                       fmaxf(redm[128 + t], redm[192 + t]));
                const float bs = reds[t] + reds[64 + t] + reds[128 + t] + reds[192 + t];
                const float nm = fmaxf(run_m, bm);
                run_s = run_s * __expf(run_m - nm) + bs * __expf(bm - nm);
                run_m = nm;
            }
            __syncthreads();

#pragma unroll
            for (int m = 0; m < 2; ++m)
#pragma unroll
                for (int n = 0; n < 4; ++n)
#pragma unroll
                    for (int e = 0; e < 4; ++e) acc[m][n][e] = 0.f;
        }
    }

    if (t < BATCH) g_pp[t * GRID_L + blk] = make_float2(run_m, run_s);
}

// ---------------- K4b: fused lse-reduce (304 partials, L2-hot) + finalize --
__global__ void __launch_bounds__(256) k_final(float* __restrict__ out) {
    const int b = blockIdx.y, t = threadIdx.x;
    const int wid = t >> 5, lane = t & 31;

    // reduce this row's 304 (m, s) partials: redundant per block, but tiny
    float m = -3.4e38f, s = 0.f;
    for (int i = t; i < GRID_L; i += 256) {
        const float2 p = g_pp[b * GRID_L + i];
        const float nm = fmaxf(m, p.x);
        s = s * __expf(m - nm) + p.y * __expf(p.x - nm);
        m = nm;
    }
#pragma unroll
    for (int o = 16; o; o >>= 1) {
        const float m2 = __shfl_xor_sync(0xffffffffu, m, o);
        const float s2 = __shfl_xor_sync(0xffffffffu, s, o);
        const float nm = fmaxf(m, m2);
        s = s * __expf(m - nm) + s2 * __expf(m2 - nm);
        m = nm;
    }
    __shared__ float sm[8], ss[8], lse_s;
    if (lane == 0) { sm[wid] = m; ss[wid] = s; }
    __syncthreads();
    if (t == 0) {
        float M = sm[0], S = ss[0];
#pragma unroll
        for (int i = 1; i < 8; ++i) {
            const float nm = fmaxf(M, sm[i]);
            S = S * __expf(M - nm) + ss[i] * __expf(sm[i] - nm);
            M = nm;
        }
        lse_s = M + logf(S);
    }
    __syncthreads();
    const float lse = lse_s;

    const int i4 = blockIdx.x * 256 + t;             // float4 index within row
    if (i4 < VOCAB / 4) {
        float4* p = (float4*)(out + (size_t)b * VOCAB) + i4;
        float4 v = *p;
        v.x -= lse; v.y -= lse; v.z -= lse; v.w -= lse;
        *p = v;
    }
}

// ---------------- launch ----------------
extern "C" void kernel_launch(void* const* d_in, const int* in_sizes, int n_in,
                              void* d_out, int out_size) {
    const int*   x  = (const int*)d_in[0];
    const int*   q  = (const int*)d_in[1];
    const float* A  = (const float*)d_in[2];
    const float* TA = (const float*)d_in[3];
    const float* TC = (const float*)d_in[4];
    float* out = (float*)d_out;

    k_gather<<<(HOPS + 1) * BSBLK, 128>>>(x, A, TA, TC);
    k_hops<<<BATCH, 128>>>(q, A);

    cudaFuncSetAttribute(k_logits, cudaFuncAttributeMaxDynamicSharedMemorySize, SMEM_LOGITS);
    k_logits<<<GRID_L, 256, SMEM_LOGITS>>>(A + (size_t)HOPS * VOCAB * EMBED, out);

    k_final<<<dim3((VOCAB / 4 + 255) / 256, BATCH), 256>>>(out);
}

// round 16
// speedup vs baseline: 1.0343x; 1.0343x over previous
#include <cuda_runtime.h>
#include <cuda_fp16.h>
#include <cstddef>
#include <cstdint>

#define VOCAB 100000
#define EMBED 128
#define STORY 50
#define SENT  64
#define BATCH 64
#define QLEN  16
#define HOPS  3

#define VT     128
#define NBLK_V ((VOCAB + VT - 1) / VT)   // 782
#define PAD    132
#define PADK   68
#define GRID_L 304
#define BSBLK  (BATCH * STORY / 4)       // 800 blocks per h-slice

// ---------------- scratch (device globals: allocation-free) ----------------
__device__ float  g_u[BATCH * EMBED];
__device__ __half g_mw[HOPS][BATCH * STORY * EMBED];   // fp16 scratch
__device__ __half g_cs[HOPS][BATCH * STORY * EMBED];
__device__ float2 g_pp[BATCH * GRID_L];                // (max, sumexp) per (b, block)
__device__ float  g_lse[BATCH];

// ---------------- mma + cp.async helpers ----------------
__device__ __forceinline__ void mma_tf32(float d[4], const uint32_t a[4],
                                         uint32_t b0, uint32_t b1) {
    asm volatile(
        "mma.sync.aligned.m16n8k8.row.col.f32.tf32.tf32.f32 "
        "{%0,%1,%2,%3}, {%4,%5,%6,%7}, {%8,%9}, {%0,%1,%2,%3};"
        : "+f"(d[0]), "+f"(d[1]), "+f"(d[2]), "+f"(d[3])
        : "r"(a[0]), "r"(a[1]), "r"(a[2]), "r"(a[3]), "r"(b0), "r"(b1));
}
__device__ __forceinline__ void cp16(uint32_t dst, const void* src) {
    asm volatile("cp.async.cg.shared.global [%0], [%1], 16;" :: "r"(dst), "l"(src));
}
#define CP_COMMIT() asm volatile("cp.async.commit_group;" ::: "memory")
#define CP_WAIT1()  asm volatile("cp.async.wait_group 1;" ::: "memory")

__device__ __forceinline__ uint32_t pack_h2(float a, float b) {
    __half2 h = __float22half2_rn(make_float2(a, b));
    return *reinterpret_cast<uint32_t*>(&h);
}

// ---------------- K2: fused gather-reduce, h-major 1D grid ----------------
__global__ void __launch_bounds__(128, 8) k_gather(const int* __restrict__ x,
                                                   const float* __restrict__ A,
                                                   const float* __restrict__ TA,
                                                   const float* __restrict__ TC) {
    const int t    = threadIdx.x;
    const int w    = t >> 5, lane = t & 31;
    const int blk  = blockIdx.x;
    const int h    = blk / BSBLK;
    const int bsb  = blk - h * BSBLK;
    const int bs   = bsb * 4 + w;
    const int s    = bs % STORY;

    __shared__ int idx[4][SENT];
    ((int*)idx)[t]       = x[bsb * 4 * SENT + t];
    ((int*)idx)[t + 128] = x[bsb * 4 * SENT + t + 128];
    __syncthreads();

    const float* __restrict__ Ah = A + (size_t)h * VOCAB * EMBED;
    const int c4 = lane * 4;

    float4 pp = make_float4(0.f, 0.f, 0.f, 0.f);   // P
    float4 ff = make_float4(0.f, 0.f, 0.f, 0.f);   // F

#pragma unroll 8
    for (int j = 0; j < SENT; ++j) {
        const float4 a = *(const float4*)(Ah + (size_t)idx[w][j] * EMBED + c4);
        const float fj = (float)(j + 1) * (1.0f / SENT);
        pp.x += a.x; pp.y += a.y; pp.z += a.z; pp.w += a.w;
        ff.x = fmaf(a.x, fj, ff.x);
        ff.y = fmaf(a.y, fj, ff.y);
        ff.z = fmaf(a.z, fj, ff.z);
        ff.w = fmaf(a.w, fj, ff.w);
    }

    if (h < HOPS) {
        const float kf0 = (float)(c4 + 1) * (1.0f / EMBED);
        const float kf1 = (float)(c4 + 2) * (1.0f / EMBED);
        const float kf2 = (float)(c4 + 3) * (1.0f / EMBED);
        const float kf3 = (float)(c4 + 4) * (1.0f / EMBED);
        const float4 ta4 = *(const float4*)(TA + s * EMBED + c4);
        float4 wp;
        wp.x = (pp.x - ff.x) - kf0 * fmaf(-2.f, ff.x, pp.x) + ta4.x;
        wp.y = (pp.y - ff.y) - kf1 * fmaf(-2.f, ff.y, pp.y) + ta4.y;
        wp.z = (pp.z - ff.z) - kf2 * fmaf(-2.f, ff.z, pp.z) + ta4.z;
        wp.w = (pp.w - ff.w) - kf3 * fmaf(-2.f, ff.w, pp.w) + ta4.w;
        const uint2 pk = make_uint2(pack_h2(wp.x, wp.y), pack_h2(wp.z, wp.w));
        __stcs(reinterpret_cast<uint2*>(g_mw[h] + (size_t)bs * EMBED + c4), pk);
    }
    if (h > 0) {
        const float4 tc4 = *(const float4*)(TC + s * EMBED + c4);
        pp.x += tc4.x; pp.y += tc4.y; pp.z += tc4.z; pp.w += tc4.w;
        const uint2 pk = make_uint2(pack_h2(pp.x, pp.y), pack_h2(pp.z, pp.w));
        __stcs(reinterpret_cast<uint2*>(g_cs[h - 1] + (size_t)bs * EMBED + c4), pk);
    }
}

// ---------------- K3: u0 + 3 hops; fp16 scratch reads, last-use (.cs) ------
__global__ void __launch_bounds__(128) k_hops(const int* __restrict__ q,
                                              const float* __restrict__ A) {
    const int b = blockIdx.x;
    const int t = threadIdx.x;     // 128
    const int w = t >> 5, lane = t & 31;

    __shared__ float u[EMBED];
    __shared__ float sc[STORY];

    {
        float acc = 0.f;
#pragma unroll
        for (int j = 0; j < QLEN; ++j) {
            const int idx = __ldg(q + b * QLEN + j);
            acc += __ldg(A + (size_t)idx * EMBED + t);
        }
        u[t] = acc;
    }
    __syncthreads();

    for (int h = 0; h < HOPS; ++h) {
        const __half* __restrict__ m = g_mw[h] + (size_t)b * STORY * EMBED;
        const __half* __restrict__ c = g_cs[h] + (size_t)b * STORY * EMBED;

        for (int s = w; s < STORY; s += 4) {
            const __half* mr = m + s * EMBED;
            float d = __half2float(__ldcs(mr + lane))      * u[lane]
                    + __half2float(__ldcs(mr + lane + 32)) * u[lane + 32]
                    + __half2float(__ldcs(mr + lane + 64)) * u[lane + 64]
                    + __half2float(__ldcs(mr + lane + 96)) * u[lane + 96];
#pragma unroll
            for (int o = 16; o; o >>= 1) d += __shfl_xor_sync(0xffffffffu, d, o);
            if (lane == 0) sc[s] = d;
        }
        __syncthreads();

        if (t < 32) {
            float v0 = sc[t];
            float v1 = (t + 32 < STORY) ? sc[t + 32] : -3.4e38f;
            float mx = fmaxf(v0, v1);
#pragma unroll
            for (int o = 16; o; o >>= 1) mx = fmaxf(mx, __shfl_xor_sync(0xffffffffu, mx, o));
            float e0 = __expf(v0 - mx);
            float e1 = (t + 32 < STORY) ? __expf(v1 - mx) : 0.f;
            float sum = e0 + e1;
#pragma unroll
            for (int o = 16; o; o >>= 1) sum += __shfl_xor_sync(0xffffffffu, sum, o);
            float inv = 1.0f / sum;
            sc[t] = e0 * inv;
            if (t + 32 < STORY) sc[t + 32] = e1 * inv;
        }
        __syncthreads();

        float acc = u[t];
        for (int s = 0; s < STORY; ++s)
            acc = fmaf(sc[s], __half2float(__ldcs(c + s * EMBED + t)), acc);
        u[t] = acc;
        __syncthreads();
    }
    g_u[b * EMBED + t] = u[t];
}

// ---------------- K4a: persistent tf32-HMMA logits, running (m,s) partials --
#define SU_F   (BATCH * PAD)           // 8448
#define SAC_F  (VT * PADK)             // 8704
#define RED_O  (SU_F + 2 * SAC_F)      // 25856
#define SMEM_LOGITS ((RED_O + 512) * 4)   // 105472

__global__ void __launch_bounds__(256, 2) k_logits(const float* __restrict__ A3,
                                                   float* __restrict__ out) {
    extern __shared__ float sh[];
    float* sU   = sh;
    float* redm = sh + RED_O;           // [4][64]
    float* reds = redm + 256;           // [4][64]

    const int t = threadIdx.x, wid = t >> 5, lane = t & 31;
    const int g = lane >> 2, t4 = lane & 3;
    const int wv = wid & 3, wb = wid >> 2;
    const int blk = blockIdx.x;

    const uint32_t smem_b = (uint32_t)__cvta_generic_to_shared(sh);
    const uint32_t sU_b   = smem_b;
    const uint32_t sA_b   = smem_b + SU_F * 4;

    int ntiles = 0;
    for (int tile = blk; tile < NBLK_V; tile += GRID_L) ++ntiles;
    if (ntiles == 0) return;
    const int S = ntiles * 2;

    auto prefA = [&](int buf, int s) {
        const int tile = blk + (s >> 1) * GRID_L;
        const int v0 = tile * VT, c = (s & 1) * 64;
        const uint32_t dst0 = sA_b + buf * (SAC_F * 4);
#pragma unroll
        for (int it = 0; it < 8; ++it) {
            const int i = t + it * 256;
            const int row = i >> 4, col = i & 15;
            int gr = v0 + row; if (gr > VOCAB - 1) gr = VOCAB - 1;
            cp16(dst0 + (row * PADK + col * 4) * 4,
                 A3 + (size_t)gr * EMBED + c + col * 4);
        }
    };

#pragma unroll
    for (int it = 0; it < 8; ++it) {
        const int i = t + it * 256;
        const int row = i >> 5, col = i & 31;
        cp16(sU_b + (row * PAD + col * 4) * 4, g_u + row * EMBED + col * 4);
    }
    prefA(0, 0);
    CP_COMMIT();
    if (S > 1) { prefA(1, 1); }
    CP_COMMIT();

    float acc[2][4][4];
#pragma unroll
    for (int m = 0; m < 2; ++m)
#pragma unroll
        for (int n = 0; n < 4; ++n)
#pragma unroll
            for (int e = 0; e < 4; ++e) acc[m][n][e] = 0.f;

    float run_m = -3.4e38f, run_s = 0.f;   // per-b running (t < BATCH only)

    const uint32_t* Ub = (const uint32_t*)sU + (wb * 32 + g) * PAD + t4;

    for (int s = 0; s < S; ++s) {
        CP_WAIT1();
        __syncthreads();

        const int buf = s & 1, ksel = s & 1;
        const uint32_t* Bb = (const uint32_t*)(sh + SU_F + buf * SAC_F)
                           + (wv * 32 + g) * PADK + t4;
        const int kofs = ksel * 64;

#pragma unroll
        for (int ks = 0; ks < 8; ++ks) {
            const int k0 = ks * 8;
            uint32_t a[2][4];
#pragma unroll
            for (int m = 0; m < 2; ++m) {
                const uint32_t* p = Ub + m * 16 * PAD + kofs + k0;
                a[m][0] = p[0];
                a[m][1] = p[8 * PAD];
                a[m][2] = p[4];
                a[m][3] = p[8 * PAD + 4];
            }
#pragma unroll
            for (int n = 0; n < 4; ++n) {
                const uint32_t* p = Bb + n * 8 * PADK + k0;
                const uint32_t b0 = p[0], b1 = p[4];
                mma_tf32(acc[0][n], a[0], b0, b1);
                mma_tf32(acc[1][n], a[1], b0, b1);
            }
        }
        __syncthreads();

        if (s + 2 < S) prefA(buf, s + 2);
        CP_COMMIT();

        if (s & 1) {
            const int tile = blk + (s >> 1) * GRID_L;
            const int v0 = tile * VT;

#pragma unroll
            for (int m = 0; m < 2; ++m) {
                const int b0r = wb * 32 + m * 16 + g;
#pragma unroll
                for (int n = 0; n < 4; ++n) {
                    const int vv = v0 + wv * 32 + n * 8 + t4 * 2;
                    if (vv < VOCAB) {
                        *(float2*)(out + (size_t)b0r * VOCAB + vv) =
                            make_float2(acc[m][n][0], acc[m][n][1]);
                        *(float2*)(out + (size_t)(b0r + 8) * VOCAB + vv) =
                            make_float2(acc[m][n][2], acc[m][n][3]);
                    }
                }
            }

#pragma unroll
            for (int m = 0; m < 2; ++m)
#pragma unroll
                for (int half = 0; half < 2; ++half) {
                    float mx = -3.4e38f;
#pragma unroll
                    for (int n = 0; n < 4; ++n) {
                        const int vv = v0 + wv * 32 + n * 8 + t4 * 2;
                        if (vv < VOCAB)
                            mx = fmaxf(mx, fmaxf(acc[m][n][half * 2],
                                                 acc[m][n][half * 2 + 1]));
                    }
                    mx = fmaxf(mx, __shfl_xor_sync(0xffffffffu, mx, 1));
                    mx = fmaxf(mx, __shfl_xor_sync(0xffffffffu, mx, 2));
                    if (t4 == 0) redm[wv * 64 + wb * 32 + m * 16 + half * 8 + g] = mx;
                }
            __syncthreads();

#pragma unroll
            for (int m = 0; m < 2; ++m)
#pragma unroll
                for (int half = 0; half < 2; ++half) {
                    const int bb = wb * 32 + m * 16 + half * 8 + g;
                    const float bm = fmaxf(fmaxf(redm[bb], redm[64 + bb]),
                                           fmaxf(redm[128 + bb], redm[192 + bb]));
                    float e = 0.f;
#pragma unroll
                    for (int n = 0; n < 4; ++n) {
                        const int vv = v0 + wv * 32 + n * 8 + t4 * 2;
                        if (vv < VOCAB)
                            e += __expf(acc[m][n][half * 2] - bm) +
                                 __expf(acc[m][n][half * 2 + 1] - bm);
                    }
                    e += __shfl_xor_sync(0xffffffffu, e, 1);
                    e += __shfl_xor_sync(0xffffffffu, e, 2);
                    if (t4 == 0) reds[wv * 64 + bb] = e;
                }
            __syncthreads();

            if (t < BATCH) {
                const float bm = fmaxf(fmaxf(redm[t], redm[64 + t]),
                                       fmaxf(redm[128 + t], redm[192 + t]));
                const float bs = reds[t] + reds[64 + t] + reds[128 + t] + reds[192 + t];
                const float nm = fmaxf(run_m, bm);
                run_s = run_s * __expf(run_m - nm) + bs * __expf(bm - nm);
                run_m = nm;
            }
            __syncthreads();

#pragma unroll
            for (int m = 0; m < 2; ++m)
#pragma unroll
                for (int n = 0; n < 4; ++n)
#pragma unroll
                    for (int e = 0; e < 4; ++e) acc[m][n][e] = 0.f;
        }
    }

    if (t < BATCH) g_pp[t * GRID_L + blk] = make_float2(run_m, run_s);
}

// ---------------- K4b: per-row logsumexp, one shuffle pass over 304 partials
__global__ void __launch_bounds__(512) k_lse() {
    const int b = blockIdx.x, t = threadIdx.x;   // 512 threads, 16 warps
    const int wid = t >> 5, lane = t & 31;

    float m = -3.4e38f, s = 0.f;
    if (t < GRID_L) {
        const float2 p = g_pp[b * GRID_L + t];
        m = p.x; s = p.y;
    }
#pragma unroll
    for (int o = 16; o; o >>= 1) {
        const float m2 = __shfl_xor_sync(0xffffffffu, m, o);
        const float s2 = __shfl_xor_sync(0xffffffffu, s, o);
        const float nm = fmaxf(m, m2);
        s = s * __expf(m - nm) + s2 * __expf(m2 - nm);
        m = nm;
    }
    __shared__ float sm[16], ss[16];
    if (lane == 0) { sm[wid] = m; ss[wid] = s; }
    __syncthreads();
    if (wid == 0) {
        m = (lane < 16) ? sm[lane] : -3.4e38f;
        s = (lane < 16) ? ss[lane] : 0.f;
#pragma unroll
        for (int o = 8; o; o >>= 1) {
            const float m2 = __shfl_xor_sync(0xffffffffu, m, o);
            const float s2 = __shfl_xor_sync(0xffffffffu, s, o);
            const float nm = fmaxf(m, m2);
            s = s * __expf(m - nm) + s2 * __expf(m2 - nm);
            m = nm;
        }
        if (lane == 0) g_lse[b] = m + logf(s);
    }
}

// ---------------- K4c: finalize out -= lse[b], 2 independent float4/thread --
__global__ void __launch_bounds__(256) k_final(float* __restrict__ out) {
    const int b  = blockIdx.y;
    const int i0 = blockIdx.x * 512 + threadIdx.x;   // float4 index within row
    const float lse = __ldg(g_lse + b);
    float4* row = (float4*)(out + (size_t)b * VOCAB);

    const bool v0 = i0 < VOCAB / 4;
    const bool v1 = i0 + 256 < VOCAB / 4;
    float4 a, c;
    if (v0) a = row[i0];
    if (v1) c = row[i0 + 256];
    if (v0) {
        a.x -= lse; a.y -= lse; a.z -= lse; a.w -= lse;
        row[i0] = a;
    }
    if (v1) {
        c.x -= lse; c.y -= lse; c.z -= lse; c.w -= lse;
        row[i0 + 256] = c;
    }
}

// ---------------- launch ----------------
extern "C" void kernel_launch(void* const* d_in, const int* in_sizes, int n_in,
                              void* d_out, int out_size) {
    const int*   x  = (const int*)d_in[0];
    const int*   q  = (const int*)d_in[1];
    const float* A  = (const float*)d_in[2];
    const float* TA = (const float*)d_in[3];
    const float* TC = (const float*)d_in[4];
    float* out = (float*)d_out;

    k_gather<<<(HOPS + 1) * BSBLK, 128>>>(x, A, TA, TC);
    k_hops<<<BATCH, 128>>>(q, A);

    cudaFuncSetAttribute(k_logits, cudaFuncAttributeMaxDynamicSharedMemorySize, SMEM_LOGITS);
    k_logits<<<GRID_L, 256, SMEM_LOGITS>>>(A + (size_t)HOPS * VOCAB * EMBED, out);

    k_lse<<<BATCH, 512>>>();
    k_final<<<dim3((VOCAB / 4 + 511) / 512, BATCH), 256>>>(out);
}

// round 17
// speedup vs baseline: 1.0389x; 1.0044x over previous
#include <cuda_runtime.h>
#include <cuda_fp16.h>
#include <cstddef>
#include <cstdint>

#define VOCAB 100000
#define EMBED 128
#define STORY 50
#define SENT  64
#define BATCH 64
#define QLEN  16
#define HOPS  3

#define VT     128
#define NBLK_V ((VOCAB + VT - 1) / VT)   // 782
#define PAD    132
#define PADK   68
#define GRID_L 304
#define BSBLK  (BATCH * STORY / 4)       // 800 blocks per h-slice

// ---------------- scratch (device globals: allocation-free) ----------------
__device__ float  g_u[BATCH * EMBED];
__device__ __half g_mw[HOPS][BATCH * STORY * EMBED];   // fp16 scratch
__device__ __half g_cs[HOPS][BATCH * STORY * EMBED];
__device__ float2 g_pp[BATCH * GRID_L];                // (max, sumexp) per (b, block)
__device__ float  g_lse[BATCH];

// ---------------- mma + cp.async helpers ----------------
__device__ __forceinline__ void mma_tf32(float d[4], const uint32_t a[4],
                                         uint32_t b0, uint32_t b1) {
    asm volatile(
        "mma.sync.aligned.m16n8k8.row.col.f32.tf32.tf32.f32 "
        "{%0,%1,%2,%3}, {%4,%5,%6,%7}, {%8,%9}, {%0,%1,%2,%3};"
        : "+f"(d[0]), "+f"(d[1]), "+f"(d[2]), "+f"(d[3])
        : "r"(a[0]), "r"(a[1]), "r"(a[2]), "r"(a[3]), "r"(b0), "r"(b1));
}
__device__ __forceinline__ void cp16(uint32_t dst, const void* src) {
    asm volatile("cp.async.cg.shared.global [%0], [%1], 16;" :: "r"(dst), "l"(src));
}
#define CP_COMMIT() asm volatile("cp.async.commit_group;" ::: "memory")
#define CP_WAIT1()  asm volatile("cp.async.wait_group 1;" ::: "memory")

__device__ __forceinline__ uint32_t pack_h2(float a, float b) {
    __half2 h = __float22half2_rn(make_float2(a, b));
    return *reinterpret_cast<uint32_t*>(&h);
}

// ---------------- K2: fused gather-reduce, h-major 1D grid ----------------
__global__ void __launch_bounds__(128, 8) k_gather(const int* __restrict__ x,
                                                   const float* __restrict__ A,
                                                   const float* __restrict__ TA,
                                                   const float* __restrict__ TC) {
    const int t    = threadIdx.x;
    const int w    = t >> 5, lane = t & 31;
    const int blk  = blockIdx.x;
    const int h    = blk / BSBLK;
    const int bsb  = blk - h * BSBLK;
    const int bs   = bsb * 4 + w;
    const int s    = bs % STORY;

    __shared__ int idx[4][SENT];
    ((int*)idx)[t]       = x[bsb * 4 * SENT + t];
    ((int*)idx)[t + 128] = x[bsb * 4 * SENT + t + 128];
    __syncthreads();

    const float* __restrict__ Ah = A + (size_t)h * VOCAB * EMBED;
    const int c4 = lane * 4;

    float4 pp = make_float4(0.f, 0.f, 0.f, 0.f);   // P
    float4 ff = make_float4(0.f, 0.f, 0.f, 0.f);   // F

#pragma unroll 8
    for (int j = 0; j < SENT; ++j) {
        const float4 a = *(const float4*)(Ah + (size_t)idx[w][j] * EMBED + c4);
        const float fj = (float)(j + 1) * (1.0f / SENT);
        pp.x += a.x; pp.y += a.y; pp.z += a.z; pp.w += a.w;
        ff.x = fmaf(a.x, fj, ff.x);
        ff.y = fmaf(a.y, fj, ff.y);
        ff.z = fmaf(a.z, fj, ff.z);
        ff.w = fmaf(a.w, fj, ff.w);
    }

    if (h < HOPS) {
        const float kf0 = (float)(c4 + 1) * (1.0f / EMBED);
        const float kf1 = (float)(c4 + 2) * (1.0f / EMBED);
        const float kf2 = (float)(c4 + 3) * (1.0f / EMBED);
        const float kf3 = (float)(c4 + 4) * (1.0f / EMBED);
        const float4 ta4 = *(const float4*)(TA + s * EMBED + c4);
        float4 wp;
        wp.x = (pp.x - ff.x) - kf0 * fmaf(-2.f, ff.x, pp.x) + ta4.x;
        wp.y = (pp.y - ff.y) - kf1 * fmaf(-2.f, ff.y, pp.y) + ta4.y;
        wp.z = (pp.z - ff.z) - kf2 * fmaf(-2.f, ff.z, pp.z) + ta4.z;
        wp.w = (pp.w - ff.w) - kf3 * fmaf(-2.f, ff.w, pp.w) + ta4.w;
        const uint2 pk = make_uint2(pack_h2(wp.x, wp.y), pack_h2(wp.z, wp.w));
        __stcs(reinterpret_cast<uint2*>(g_mw[h] + (size_t)bs * EMBED + c4), pk);
    }
    if (h > 0) {
        const float4 tc4 = *(const float4*)(TC + s * EMBED + c4);
        pp.x += tc4.x; pp.y += tc4.y; pp.z += tc4.z; pp.w += tc4.w;
        const uint2 pk = make_uint2(pack_h2(pp.x, pp.y), pack_h2(pp.z, pp.w));
        __stcs(reinterpret_cast<uint2*>(g_cs[h - 1] + (size_t)bs * EMBED + c4), pk);
    }
}

// ---------------- K3: u0 + 3 hops, 256 threads (halved latency chains) ------
__global__ void __launch_bounds__(256) k_hops(const int* __restrict__ q,
                                              const float* __restrict__ A) {
    const int b = blockIdx.x;
    const int t = threadIdx.x;          // 256
    const int w = t >> 5, lane = t & 31;
    const int hid = t >> 7;             // 0 or 1
    const int d   = t & 127;

    __shared__ float u[EMBED];
    __shared__ float upart[2][EMBED];
    __shared__ float sc[STORY];

    // u0 = sum_j A[0][q[b,j]], split j-range across halves
    {
        float acc = 0.f;
#pragma unroll
        for (int j = hid * 8; j < hid * 8 + 8; ++j) {
            const int idx = __ldg(q + b * QLEN + j);
            acc += __ldg(A + (size_t)idx * EMBED + d);
        }
        upart[hid][d] = acc;
    }
    __syncthreads();
    if (t < EMBED) u[t] = upart[0][t] + upart[1][t];
    __syncthreads();

    for (int h = 0; h < HOPS; ++h) {
        const __half* __restrict__ m = g_mw[h] + (size_t)b * STORY * EMBED;
        const __half* __restrict__ c = g_cs[h] + (size_t)b * STORY * EMBED;

        // scores: 8 warps, ~6-7 s each
        for (int s = w; s < STORY; s += 8) {
            const __half* mr = m + s * EMBED;
            float dd = __half2float(__ldcs(mr + lane))      * u[lane]
                     + __half2float(__ldcs(mr + lane + 32)) * u[lane + 32]
                     + __half2float(__ldcs(mr + lane + 64)) * u[lane + 64]
                     + __half2float(__ldcs(mr + lane + 96)) * u[lane + 96];
#pragma unroll
            for (int o = 16; o; o >>= 1) dd += __shfl_xor_sync(0xffffffffu, dd, o);
            if (lane == 0) sc[s] = dd;
        }
        __syncthreads();

        // softmax over STORY=50 (warp 0)
        if (t < 32) {
            float v0 = sc[t];
            float v1 = (t + 32 < STORY) ? sc[t + 32] : -3.4e38f;
            float mx = fmaxf(v0, v1);
#pragma unroll
            for (int o = 16; o; o >>= 1) mx = fmaxf(mx, __shfl_xor_sync(0xffffffffu, mx, o));
            float e0 = __expf(v0 - mx);
            float e1 = (t + 32 < STORY) ? __expf(v1 - mx) : 0.f;
            float sum = e0 + e1;
#pragma unroll
            for (int o = 16; o; o >>= 1) sum += __shfl_xor_sync(0xffffffffu, sum, o);
            float inv = 1.0f / sum;
            sc[t] = e0 * inv;
            if (t + 32 < STORY) sc[t + 32] = e1 * inv;
        }
        __syncthreads();

        // u update: split s even/odd across halves (25-long chains)
        {
            float acc = 0.f;
            for (int s = hid; s < STORY; s += 2)
                acc = fmaf(sc[s], __half2float(__ldcs(c + s * EMBED + d)), acc);
            upart[hid][d] = acc;
        }
        __syncthreads();
        if (t < EMBED) u[t] = u[t] + upart[0][t] + upart[1][t];
        __syncthreads();
    }
    if (t < EMBED) g_u[b * EMBED + t] = u[t];
}

// ---------------- K4a: persistent tf32-HMMA logits, running (m,s) partials --
#define SU_F   (BATCH * PAD)           // 8448
#define SAC_F  (VT * PADK)             // 8704
#define RED_O  (SU_F + 2 * SAC_F)      // 25856
#define SMEM_LOGITS ((RED_O + 512) * 4)   // 105472

__global__ void __launch_bounds__(256, 2) k_logits(const float* __restrict__ A3,
                                                   float* __restrict__ out) {
    extern __shared__ float sh[];
    float* sU   = sh;
    float* redm = sh + RED_O;           // [4][64]
    float* reds = redm + 256;           // [4][64]

    const int t = threadIdx.x, wid = t >> 5, lane = t & 31;
    const int g = lane >> 2, t4 = lane & 3;
    const int wv = wid & 3, wb = wid >> 2;
    const int blk = blockIdx.x;

    const uint32_t smem_b = (uint32_t)__cvta_generic_to_shared(sh);
    const uint32_t sU_b   = smem_b;
    const uint32_t sA_b   = smem_b + SU_F * 4;

    int ntiles = 0;
    for (int tile = blk; tile < NBLK_V; tile += GRID_L) ++ntiles;
    if (ntiles == 0) return;
    const int S = ntiles * 2;

    auto prefA = [&](int buf, int s) {
        const int tile = blk + (s >> 1) * GRID_L;
        const int v0 = tile * VT, c = (s & 1) * 64;
        const uint32_t dst0 = sA_b + buf * (SAC_F * 4);
#pragma unroll
        for (int it = 0; it < 8; ++it) {
            const int i = t + it * 256;
            const int row = i >> 4, col = i & 15;
            int gr = v0 + row; if (gr > VOCAB - 1) gr = VOCAB - 1;
            cp16(dst0 + (row * PADK + col * 4) * 4,
                 A3 + (size_t)gr * EMBED + c + col * 4);
        }
    };

#pragma unroll
    for (int it = 0; it < 8; ++it) {
        const int i = t + it * 256;
        const int row = i >> 5, col = i & 31;
        cp16(sU_b + (row * PAD + col * 4) * 4, g_u + row * EMBED + col * 4);
    }
    prefA(0, 0);
    CP_COMMIT();
    if (S > 1) { prefA(1, 1); }
    CP_COMMIT();

    float acc[2][4][4];
#pragma unroll
    for (int m = 0; m < 2; ++m)
#pragma unroll
        for (int n = 0; n < 4; ++n)
#pragma unroll
            for (int e = 0; e < 4; ++e) acc[m][n][e] = 0.f;

    float run_m = -3.4e38f, run_s = 0.f;   // per-b running (t < BATCH only)

    const uint32_t* Ub = (const uint32_t*)sU + (wb * 32 + g) * PAD + t4;

    for (int s = 0; s < S; ++s) {
        CP_WAIT1();
        __syncthreads();

        const int buf = s & 1, ksel = s & 1;
        const uint32_t* Bb = (const uint32_t*)(sh + SU_F + buf * SAC_F)
                           + (wv * 32 + g) * PADK + t4;
        const int kofs = ksel * 64;

#pragma unroll
        for (int ks = 0; ks < 8; ++ks) {
            const int k0 = ks * 8;
            uint32_t a[2][4];
#pragma unroll
            for (int m = 0; m < 2; ++m) {
                const uint32_t* p = Ub + m * 16 * PAD + kofs + k0;
                a[m][0] = p[0];
                a[m][1] = p[8 * PAD];
                a[m][2] = p[4];
                a[m][3] = p[8 * PAD + 4];
            }
#pragma unroll
            for (int n = 0; n < 4; ++n) {
                const uint32_t* p = Bb + n * 8 * PADK + k0;
                const uint32_t b0 = p[0], b1 = p[4];
                mma_tf32(acc[0][n], a[0], b0, b1);
                mma_tf32(acc[1][n], a[1], b0, b1);
            }
        }
        __syncthreads();

        if (s + 2 < S) prefA(buf, s + 2);
        CP_COMMIT();

        if (s & 1) {
            const int tile = blk + (s >> 1) * GRID_L;
            const int v0 = tile * VT;

#pragma unroll
            for (int m = 0; m < 2; ++m) {
                const int b0r = wb * 32 + m * 16 + g;
#pragma unroll
                for (int n = 0; n < 4; ++n) {
                    const int vv = v0 + wv * 32 + n * 8 + t4 * 2;
                    if (vv < VOCAB) {
                        *(float2*)(out + (size_t)b0r * VOCAB + vv) =
                            make_float2(acc[m][n][0], acc[m][n][1]);
                        *(float2*)(out + (size_t)(b0r + 8) * VOCAB + vv) =
                            make_float2(acc[m][n][2], acc[m][n][3]);
                    }
                }
            }

#pragma unroll
            for (int m = 0; m < 2; ++m)
#pragma unroll
                for (int half = 0; half < 2; ++half) {
                    float mx = -3.4e38f;
#pragma unroll
                    for (int n = 0; n < 4; ++n) {
                        const int vv = v0 + wv * 32 + n * 8 + t4 * 2;
                        if (vv < VOCAB)
                            mx = fmaxf(mx, fmaxf(acc[m][n][half * 2],
                                                 acc[m][n][half * 2 + 1]));
                    }
                    mx = fmaxf(mx, __shfl_xor_sync(0xffffffffu, mx, 1));
                    mx = fmaxf(mx, __shfl_xor_sync(0xffffffffu, mx, 2));
                    if (t4 == 0) redm[wv * 64 + wb * 32 + m * 16 + half * 8 + g] = mx;
                }
            __syncthreads();

#pragma unroll
            for (int m = 0; m < 2; ++m)
#pragma unroll
                for (int half = 0; half < 2; ++half) {
                    const int bb = wb * 32 + m * 16 + half * 8 + g;
                    const float bm = fmaxf(fmaxf(redm[bb], redm[64 + bb]),
                                           fmaxf(redm[128 + bb], redm[192 + bb]));
                    float e = 0.f;
#pragma unroll
                    for (int n = 0; n < 4; ++n) {
                        const int vv = v0 + wv * 32 + n * 8 + t4 * 2;
                        if (vv < VOCAB)
                            e += __expf(acc[m][n][half * 2] - bm) +
                                 __expf(acc[m][n][half * 2 + 1] - bm);
                    }
                    e += __shfl_xor_sync(0xffffffffu, e, 1);
                    e += __shfl_xor_sync(0xffffffffu, e, 2);
                    if (t4 == 0) reds[wv * 64 + bb] = e;
                }
            __syncthreads();

            if (t < BATCH) {
                const float bm = fmaxf(fmaxf(redm[t], redm[64 + t]),
                                       fmaxf(redm[128 + t], redm[192 + t]));
                const float bs = reds[t] + reds[64 + t] + reds[128 + t] + reds[192 + t];
                const float nm = fmaxf(run_m, bm);
                run_s = run_s * __expf(run_m - nm) + bs * __expf(bm - nm);
                run_m = nm;
            }
            __syncthreads();

#pragma unroll
            for (int m = 0; m < 2; ++m)
#pragma unroll
                for (int n = 0; n < 4; ++n)
#pragma unroll
                    for (int e = 0; e < 4; ++e) acc[m][n][e] = 0.f;
        }
    }

    if (t < BATCH) g_pp[t * GRID_L + blk] = make_float2(run_m, run_s);
}

// ---------------- K4b: per-row logsumexp, one shuffle pass over 304 partials
__global__ void __launch_bounds__(512) k_lse() {
    const int b = blockIdx.x, t = threadIdx.x;   // 512 threads, 16 warps
    const int wid = t >> 5, lane = t & 31;

    float m = -3.4e38f, s = 0.f;
    if (t < GRID_L) {
        const float2 p = g_pp[b * GRID_L + t];
        m = p.x; s = p.y;
    }
#pragma unroll
    for (int o = 16; o; o >>= 1) {
        const float m2 = __shfl_xor_sync(0xffffffffu, m, o);
        const float s2 = __shfl_xor_sync(0xffffffffu, s, o);
        const float nm = fmaxf(m, m2);
        s = s * __expf(m - nm) + s2 * __expf(m2 - nm);
        m = nm;
    }
    __shared__ float sm[16], ss[16];
    if (lane == 0) { sm[wid] = m; ss[wid] = s; }
    __syncthreads();
    if (wid == 0) {
        m = (lane < 16) ? sm[lane] : -3.4e38f;
        s = (lane < 16) ? ss[lane] : 0.f;
#pragma unroll
        for (int o = 8; o; o >>= 1) {
            const float m2 = __shfl_xor_sync(0xffffffffu, m, o);
            const float s2 = __shfl_xor_sync(0xffffffffu, s, o);
            const float nm = fmaxf(m, m2);
            s = s * __expf(m - nm) + s2 * __expf(m2 - nm);
            m = nm;
        }
        if (lane == 0) g_lse[b] = m + logf(s);
    }
}

// ---------------- K4c: finalize out -= lse[b], 2 independent float4/thread --
__global__ void __launch_bounds__(256) k_final(float* __restrict__ out) {
    const int b  = blockIdx.y;
    const int i0 = blockIdx.x * 512 + threadIdx.x;   // float4 index within row
    const float lse = __ldg(g_lse + b);
    float4* row = (float4*)(out + (size_t)b * VOCAB);

    const bool v0 = i0 < VOCAB / 4;
    const bool v1 = i0 + 256 < VOCAB / 4;
    float4 a, c;
    if (v0) a = row[i0];
    if (v1) c = row[i0 + 256];
    if (v0) {
        a.x -= lse; a.y -= lse; a.z -= lse; a.w -= lse;
        row[i0] = a;
    }
    if (v1) {
        c.x -= lse; c.y -= lse; c.z -= lse; c.w -= lse;
        row[i0 + 256] = c;
    }
}

// ---------------- launch ----------------
extern "C" void kernel_launch(void* const* d_in, const int* in_sizes, int n_in,
                              void* d_out, int out_size) {
    const int*   x  = (const int*)d_in[0];
    const int*   q  = (const int*)d_in[1];
    const float* A  = (const float*)d_in[2];
    const float* TA = (const float*)d_in[3];
    const float* TC = (const float*)d_in[4];
    float* out = (float*)d_out;

    k_gather<<<(HOPS + 1) * BSBLK, 128>>>(x, A, TA, TC);
    k_hops<<<BATCH, 256>>>(q, A);

    cudaFuncSetAttribute(k_logits, cudaFuncAttributeMaxDynamicSharedMemorySize, SMEM_LOGITS);
    k_logits<<<GRID_L, 256, SMEM_LOGITS>>>(A + (size_t)HOPS * VOCAB * EMBED, out);

    k_lse<<<BATCH, 512>>>();
    k_final<<<dim3((VOCAB / 4 + 511) / 512, BATCH), 256>>>(out);
}